// round 11
// baseline (speedup 1.0000x reference)
#include <cuda_runtime.h>

#define B_ 256
#define S_ 197
#define D_ 768
#define D4_ 192
#define P_ 20
#define L_ 5
#define T_ 10
#define K_ 5
#define ROWS_TOK 75            // (T+K)*L
#define ROWS_ASSIST 50         // T*L
#define ROWS_SEL 25            // K*L
#define ROWS_PE 272            // ROWS_TOK + S
#define Q_ 8                   // mean/copy chunks per batch row
#define CHUNK 25               // rows per chunk (last chunk = 22)
#define RSB 16                 // reduce_sim blocks (16 b's each)

// float offsets into d_out
#define PE_OFF   0ULL
#define SIM_OFF  53477376ULL
#define TOK_OFF  53477377ULL
#define IDX_OFF  68222977ULL
#define XN_OFF   68224257ULL

// scratch (device globals; no allocations)
__device__ float g_part[Q_ * B_ * D_];
__device__ float g_xnorm[B_ * D_];
__device__ float g_pnorm[P_ * D_];
__device__ int   g_idx[B_ * K_];
__device__ int   g_cnt[P_];

// 192-thread block reduce (padded to 256 in shared)
__device__ __forceinline__ float blk_reduce_192(float v) {
    __shared__ float sh[256];
    int t = threadIdx.x;
    sh[t] = v;
    if (t < 64) sh[192 + t] = 0.f;
    __syncthreads();
    for (int s = 128; s > 0; s >>= 1) {
        if (t < s) sh[t] += sh[t + s];
        __syncthreads();
    }
    return sh[0];
}

// Write one 768-float row (staged in shared, `srow`) to out at float offset g0,
// where g0 % 4 == 1. Emits 191 aligned float4 stores + 4 edge scalars.
__device__ __forceinline__ void store_row_aligned(float* __restrict__ out,
                                                  size_t g0,
                                                  const float* __restrict__ srow,
                                                  int t) {
    if (t < 191) {
        float4 w = make_float4(srow[3 + 4 * t], srow[4 + 4 * t],
                               srow[5 + 4 * t], srow[6 + 4 * t]);
        __stcs((float4*)(out + g0 + 3) + t, w);
    } else {
        __stcs(out + g0 + 0, srow[0]);
        __stcs(out + g0 + 1, srow[1]);
        __stcs(out + g0 + 2, srow[2]);
        __stcs(out + g0 + 767, srow[767]);
    }
}

// ---------------------------------------------------------------------------
// Kernel 1: grid (B, Q_+3), block 192.
//  q<Q_   : stream x_embed chunk -> prompted_embedding[:, 75:, :] + partials.
//  q==Q_  : b<P -> l2-normalize prompt_key row b; b==0 zeroes g_cnt + SIM slot.
//  q>Q_   : 25 assist rows -> prompted_embedding AND tokens (aligned stores).
// ---------------------------------------------------------------------------
__global__ void k_mean_copy(const float4* __restrict__ x,
                            const float4* __restrict__ pk,
                            const float4* __restrict__ assist,
                            float* __restrict__ out) {
    int b = blockIdx.x;
    int q = blockIdx.y;
    int t = threadIdx.x;                 // 0..191

    if (q == Q_) {
        if (b == 0 && t < P_) g_cnt[t] = 0;
        if (b == 0 && t == 0) out[SIM_OFF] = 0.f;
        if (b < P_) {
            float4 v = pk[(size_t)b * D4_ + t];
            float ss = blk_reduce_192(v.x * v.x + v.y * v.y + v.z * v.z + v.w * v.w);
            float r = rsqrtf(fmaxf(ss, 1e-12f));
            float4 n = make_float4(v.x * r, v.y * r, v.z * r, v.w * r);
            ((float4*)g_pnorm)[(size_t)b * D4_ + t] = n;
        }
        cudaTriggerProgrammaticLaunchCompletion();
        return;
    }

    if (q > Q_) {
        // 25 assist rows [r0, r0+25) for batch b -> PE (aligned) + TOK (staged)
        __shared__ float srow[D_];
        int r0 = (q - Q_ - 1) * 25;
        float4* pe = (float4*)(out + PE_OFF) + (size_t)b * ROWS_PE * D4_ + t;
        size_t tok0 = TOK_OFF + (size_t)b * ROWS_TOK * D_;
        for (int i = 0; i < 25; i++) {
            int r = r0 + i;
            float4 v = assist[(size_t)r * D4_ + t];
            __stcs(pe + (size_t)r * D4_, v);
            *(float4*)&srow[4 * t] = v;
            __syncthreads();
            store_row_aligned(out, tok0 + (size_t)r * D_, srow, t);
            __syncthreads();
        }
        cudaTriggerProgrammaticLaunchCompletion();
        return;
    }

    int s0 = q * CHUNK;
    int s1 = (q == Q_ - 1) ? S_ : s0 + CHUNK;

    const float4* xb = x + (size_t)b * S_ * D4_ + t;
    float4* ob = ((float4*)(out + PE_OFF)) + (size_t)b * ROWS_PE * D4_ + (size_t)ROWS_TOK * D4_ + t;

    float4 acc = make_float4(0.f, 0.f, 0.f, 0.f);
    int s = s0;
    for (; s + 5 <= s1; s += 5) {
        float4 v0 = __ldcs(xb + (size_t)(s + 0) * D4_);
        float4 v1 = __ldcs(xb + (size_t)(s + 1) * D4_);
        float4 v2 = __ldcs(xb + (size_t)(s + 2) * D4_);
        float4 v3 = __ldcs(xb + (size_t)(s + 3) * D4_);
        float4 v4 = __ldcs(xb + (size_t)(s + 4) * D4_);
        acc.x += v0.x + v1.x + v2.x + v3.x + v4.x;
        acc.y += v0.y + v1.y + v2.y + v3.y + v4.y;
        acc.z += v0.z + v1.z + v2.z + v3.z + v4.z;
        acc.w += v0.w + v1.w + v2.w + v3.w + v4.w;
        __stcs(ob + (size_t)(s + 0) * D4_, v0);
        __stcs(ob + (size_t)(s + 1) * D4_, v1);
        __stcs(ob + (size_t)(s + 2) * D4_, v2);
        __stcs(ob + (size_t)(s + 3) * D4_, v3);
        __stcs(ob + (size_t)(s + 4) * D4_, v4);
    }
    for (; s < s1; s++) {
        float4 v = __ldcs(xb + (size_t)s * D4_);
        acc.x += v.x; acc.y += v.y; acc.z += v.z; acc.w += v.w;
        __stcs(ob + (size_t)s * D4_, v);
    }
    ((float4*)g_part)[(size_t)q * B_ * D4_ + (size_t)b * D4_ + t] = acc;
    cudaTriggerProgrammaticLaunchCompletion();
}

// ---------------------------------------------------------------------------
// Kernel 2: grid B, block 192. PDL secondary of k1.
// Triggers k3 launch immediately, waits on k1, combines partials -> mean ->
// l2norm -> x_norm out (aligned); 20 similarity dots; top-5 / idx / counts.
// ---------------------------------------------------------------------------
__global__ void k_xnorm_topk(float* __restrict__ out) {
    __shared__ float  sh[256];
    __shared__ float4 shx[D4_];
    __shared__ float  shsim[P_];
    int b = blockIdx.x;
    int t = threadIdx.x;

    cudaTriggerProgrammaticLaunchCompletion();
    cudaGridDependencySynchronize();             // wait for k1's g_part/g_pnorm

    const float4* part = (const float4*)g_part + (size_t)b * D4_ + t;
    float4 a = make_float4(0.f, 0.f, 0.f, 0.f);
#pragma unroll
    for (int q = 0; q < Q_; q++) {
        float4 c = part[(size_t)q * B_ * D4_];
        a.x += c.x; a.y += c.y; a.z += c.z; a.w += c.w;
    }
    const float inv = 1.0f / (float)S_;
    a.x *= inv; a.y *= inv; a.z *= inv; a.w *= inv;

    sh[t] = a.x * a.x + a.y * a.y + a.z * a.z + a.w * a.w;
    if (t < 64) sh[192 + t] = 0.f;
    __syncthreads();
    for (int s = 128; s > 0; s >>= 1) {
        if (t < s) sh[t] += sh[t + s];
        __syncthreads();
    }
    float r = rsqrtf(fmaxf(sh[0], 1e-12f));
    float4 n = make_float4(a.x * r, a.y * r, a.z * r, a.w * r);

    ((float4*)g_xnorm)[(size_t)b * D4_ + t] = n;

    shx[t] = n;
    __syncthreads();

    // x_norm output (row start ≡ 1 mod 4) — aligned stores from shared
    store_row_aligned(out, XN_OFF + (size_t)b * D_, (const float*)shx, t);

    int w = t >> 5;          // 0..5
    int lane = t & 31;
    for (int p = w; p < P_; p += 6) {
        const float4* pn = ((const float4*)g_pnorm) + (size_t)p * D4_;
        float acc = 0.f;
#pragma unroll
        for (int i = 0; i < 6; i++) {
            int j = lane + 32 * i;
            float4 pv = pn[j];
            float4 xv = shx[j];
            acc += xv.x * pv.x + xv.y * pv.y + xv.z * pv.z + xv.w * pv.w;
        }
#pragma unroll
        for (int off = 16; off > 0; off >>= 1)
            acc += __shfl_down_sync(0xffffffffu, acc, off);
        if (lane == 0) shsim[p] = acc;
    }
    __syncthreads();

    if (t == 0) {
        float sim[P_];
        bool used[P_];
#pragma unroll
        for (int p = 0; p < P_; p++) { sim[p] = shsim[p]; used[p] = false; }
        for (int k = 0; k < K_; k++) {
            float best = -3.4e38f;
            int bi = 0;
#pragma unroll
            for (int p = 0; p < P_; p++) {
                if (!used[p] && sim[p] > best) { best = sim[p]; bi = p; }
            }
            used[bi] = true;
            bool keep = best > 0.0f;
            int idxp = keep ? bi : -1;
            g_idx[b * K_ + k] = idxp;
            out[IDX_OFF + (size_t)b * K_ + k] = (float)idxp;
            if (keep) atomicAdd(&g_cnt[bi], 1);
        }
    }
}

// ---------------------------------------------------------------------------
// Kernel 3: grid (26, B), block 192. PDL secondary of k2.
//  r<25        : selected-prompt row (sync on k2) -> PE + TOK (aligned).
//  r==25, b<16 : sync on k2, reduce_sim partial, atomicAdd to SIM slot.
// ---------------------------------------------------------------------------
__global__ void k_sel(const float4* __restrict__ prompt,
                      float* __restrict__ out) {
    __shared__ float srow[D_];
    int r = blockIdx.x;      // 0..25
    int b = blockIdx.y;
    int t = threadIdx.x;     // 0..191

    if (r == ROWS_SEL) {
        if (b >= RSB) return;
        cudaGridDependencySynchronize();
        const float4* xn = (const float4*)g_xnorm + (size_t)(b * 16) * D4_ + t;
        float4 sx = make_float4(0.f, 0.f, 0.f, 0.f);
#pragma unroll
        for (int i = 0; i < 16; i++) {
            float4 v = xn[(size_t)i * D4_];
            sx.x += v.x; sx.y += v.y; sx.z += v.z; sx.w += v.w;
        }
        float4 kt = make_float4(0.f, 0.f, 0.f, 0.f);
#pragma unroll
        for (int p = 0; p < P_; p++) {
            float c = (float)g_cnt[p];
            float4 v = ((const float4*)g_pnorm)[(size_t)p * D4_ + t];
            kt.x += c * v.x; kt.y += c * v.y; kt.z += c * v.z; kt.w += c * v.w;
        }
        float partial = sx.x * kt.x + sx.y * kt.y + sx.z * kt.z + sx.w * kt.w;
        float tot = blk_reduce_192(partial);
        if (t == 0) atomicAdd(out + SIM_OFF, tot * (1.0f / (float)B_));
        return;
    }

    cudaGridDependencySynchronize();
    int idx = g_idx[b * K_ + r / L_];
    float4 v = make_float4(0.f, 0.f, 0.f, 0.f);
    if (idx >= 0)
        v = prompt[((size_t)idx * L_ + (r % L_)) * D4_ + t];

    int row = ROWS_ASSIST + r;
    __stcs((float4*)(out + PE_OFF) + (size_t)b * ROWS_PE * D4_ + (size_t)row * D4_ + t, v);

    *(float4*)&srow[4 * t] = v;
    __syncthreads();
    store_row_aligned(out, TOK_OFF + (size_t)b * ROWS_TOK * D_ + (size_t)row * D_, srow, t);
}

extern "C" void kernel_launch(void* const* d_in, const int* in_sizes, int n_in,
                              void* d_out, int out_size) {
    const float4* x_embed = (const float4*)d_in[0];        // [B,S,D]
    const float4* prompt = (const float4*)d_in[1];         // [P,L,D]
    const float4* prompt_key = (const float4*)d_in[2];     // [P,D]
    const float4* assist = (const float4*)d_in[3];         // [T,L,D]
    float* out = (float*)d_out;

    k_mean_copy<<<dim3(B_, Q_ + 3), D4_>>>(x_embed, prompt_key, assist, out);

    cudaLaunchAttribute attr[1];
    attr[0].id = cudaLaunchAttributeProgrammaticStreamSerialization;
    attr[0].val.programmaticStreamSerializationAllowed = 1;

    {
        cudaLaunchConfig_t cfg = {};
        cfg.gridDim = dim3(B_, 1, 1);
        cfg.blockDim = dim3(D4_, 1, 1);
        cfg.stream = 0;
        cfg.attrs = attr;
        cfg.numAttrs = 1;
        cudaLaunchKernelEx(&cfg, k_xnorm_topk, out);
    }
    {
        cudaLaunchConfig_t cfg = {};
        cfg.gridDim = dim3(ROWS_SEL + 1, B_, 1);
        cfg.blockDim = dim3(D4_, 1, 1);
        cfg.stream = 0;
        cfg.attrs = attr;
        cfg.numAttrs = 1;
        cudaLaunchKernelEx(&cfg, k_sel, prompt, out);
    }
}

// round 12
// speedup vs baseline: 1.0591x; 1.0591x over previous
#include <cuda_runtime.h>

#define B_ 256
#define S_ 197
#define D_ 768
#define D4_ 192
#define P_ 20
#define L_ 5
#define T_ 10
#define K_ 5
#define ROWS_TOK 75            // (T+K)*L
#define ROWS_ASSIST 50         // T*L
#define ROWS_PE 272            // ROWS_TOK + S
#define Q_ 8                   // mean/copy chunks per batch row
#define CHUNK 25               // rows per chunk (last chunk = 22)
#define RSB 16                 // reduce_sim blocks (16 b's each)
#define BB 8                   // batches per k3 block

// float offsets into d_out
#define PE_OFF   0ULL
#define SIM_OFF  53477376ULL
#define TOK_OFF  53477377ULL
#define IDX_OFF  68222977ULL
#define XN_OFF   68224257ULL

// scratch (device globals; no allocations)
__device__ float g_part[Q_ * B_ * D_];
__device__ float g_xnorm[B_ * D_];
__device__ float g_pnorm[P_ * D_];
__device__ int   g_idx[B_ * K_];
__device__ int   g_cnt[P_];

// 192-thread block reduce (padded to 256 in shared)
__device__ __forceinline__ float blk_reduce_192(float v) {
    __shared__ float sh[256];
    int t = threadIdx.x;
    sh[t] = v;
    if (t < 64) sh[192 + t] = 0.f;
    __syncthreads();
    for (int s = 128; s > 0; s >>= 1) {
        if (t < s) sh[t] += sh[t + s];
        __syncthreads();
    }
    return sh[0];
}

// Write one 768-float row (staged in shared, `srow`) to out at float offset g0,
// where g0 % 4 == 1. Emits 191 aligned float4 stores + 4 edge scalars.
__device__ __forceinline__ void store_row_aligned(float* __restrict__ out,
                                                  size_t g0,
                                                  const float* __restrict__ srow,
                                                  int t) {
    if (t < 191) {
        float4 w = make_float4(srow[3 + 4 * t], srow[4 + 4 * t],
                               srow[5 + 4 * t], srow[6 + 4 * t]);
        __stcs((float4*)(out + g0 + 3) + t, w);
    } else {
        __stcs(out + g0 + 0, srow[0]);
        __stcs(out + g0 + 1, srow[1]);
        __stcs(out + g0 + 2, srow[2]);
        __stcs(out + g0 + 767, srow[767]);
    }
}

// ---------------------------------------------------------------------------
// Kernel 1: grid (B, Q_+1), block 192.  (R10-identical; proven at BW floor)
//  q<Q_ : stream x_embed rows chunk -> prompted_embedding[:, 75:, :] + partials.
//  q==Q_: b<P -> l2-normalize prompt_key row b; b==0 zeroes g_cnt + SIM slot.
// ---------------------------------------------------------------------------
__global__ void k_mean_copy(const float4* __restrict__ x,
                            const float4* __restrict__ pk,
                            float* __restrict__ out) {
    int b = blockIdx.x;
    int q = blockIdx.y;
    int t = threadIdx.x;                 // 0..191

    if (q == Q_) {
        if (b == 0 && t < P_) g_cnt[t] = 0;
        if (b == 0 && t == 0) out[SIM_OFF] = 0.f;
        if (b < P_) {
            float4 v = pk[(size_t)b * D4_ + t];
            float ss = blk_reduce_192(v.x * v.x + v.y * v.y + v.z * v.z + v.w * v.w);
            float r = rsqrtf(fmaxf(ss, 1e-12f));
            float4 n = make_float4(v.x * r, v.y * r, v.z * r, v.w * r);
            ((float4*)g_pnorm)[(size_t)b * D4_ + t] = n;
        }
        cudaTriggerProgrammaticLaunchCompletion();
        return;
    }

    int s0 = q * CHUNK;
    int s1 = (q == Q_ - 1) ? S_ : s0 + CHUNK;

    const float4* xb = x + (size_t)b * S_ * D4_ + t;
    float4* ob = ((float4*)(out + PE_OFF)) + (size_t)b * ROWS_PE * D4_ + (size_t)ROWS_TOK * D4_ + t;

    float4 acc = make_float4(0.f, 0.f, 0.f, 0.f);
    int s = s0;
    for (; s + 5 <= s1; s += 5) {
        float4 v0 = __ldcs(xb + (size_t)(s + 0) * D4_);
        float4 v1 = __ldcs(xb + (size_t)(s + 1) * D4_);
        float4 v2 = __ldcs(xb + (size_t)(s + 2) * D4_);
        float4 v3 = __ldcs(xb + (size_t)(s + 3) * D4_);
        float4 v4 = __ldcs(xb + (size_t)(s + 4) * D4_);
        acc.x += v0.x + v1.x + v2.x + v3.x + v4.x;
        acc.y += v0.y + v1.y + v2.y + v3.y + v4.y;
        acc.z += v0.z + v1.z + v2.z + v3.z + v4.z;
        acc.w += v0.w + v1.w + v2.w + v3.w + v4.w;
        __stcs(ob + (size_t)(s + 0) * D4_, v0);
        __stcs(ob + (size_t)(s + 1) * D4_, v1);
        __stcs(ob + (size_t)(s + 2) * D4_, v2);
        __stcs(ob + (size_t)(s + 3) * D4_, v3);
        __stcs(ob + (size_t)(s + 4) * D4_, v4);
    }
    for (; s < s1; s++) {
        float4 v = __ldcs(xb + (size_t)s * D4_);
        acc.x += v.x; acc.y += v.y; acc.z += v.z; acc.w += v.w;
        __stcs(ob + (size_t)s * D4_, v);
    }
    ((float4*)g_part)[(size_t)q * B_ * D4_ + (size_t)b * D4_ + t] = acc;
    cudaTriggerProgrammaticLaunchCompletion();
}

// ---------------------------------------------------------------------------
// Kernel 2: grid B, block 192. PDL secondary of k1. (R10-identical)
// ---------------------------------------------------------------------------
__global__ void k_xnorm_topk(float* __restrict__ out) {
    __shared__ float  sh[256];
    __shared__ float4 shx[D4_];
    __shared__ float  shsim[P_];
    int b = blockIdx.x;
    int t = threadIdx.x;

    cudaTriggerProgrammaticLaunchCompletion();   // let k3's assist blocks start
    cudaGridDependencySynchronize();             // wait for k1's g_part/g_pnorm

    const float4* part = (const float4*)g_part + (size_t)b * D4_ + t;
    float4 a = make_float4(0.f, 0.f, 0.f, 0.f);
#pragma unroll
    for (int q = 0; q < Q_; q++) {
        float4 c = part[(size_t)q * B_ * D4_];
        a.x += c.x; a.y += c.y; a.z += c.z; a.w += c.w;
    }
    const float inv = 1.0f / (float)S_;
    a.x *= inv; a.y *= inv; a.z *= inv; a.w *= inv;

    sh[t] = a.x * a.x + a.y * a.y + a.z * a.z + a.w * a.w;
    if (t < 64) sh[192 + t] = 0.f;
    __syncthreads();
    for (int s = 128; s > 0; s >>= 1) {
        if (t < s) sh[t] += sh[t + s];
        __syncthreads();
    }
    float r = rsqrtf(fmaxf(sh[0], 1e-12f));
    float4 n = make_float4(a.x * r, a.y * r, a.z * r, a.w * r);

    ((float4*)g_xnorm)[(size_t)b * D4_ + t] = n;

    shx[t] = n;
    __syncthreads();

    store_row_aligned(out, XN_OFF + (size_t)b * D_, (const float*)shx, t);

    int w = t >> 5;          // 0..5
    int lane = t & 31;
    for (int p = w; p < P_; p += 6) {
        const float4* pn = ((const float4*)g_pnorm) + (size_t)p * D4_;
        float acc = 0.f;
#pragma unroll
        for (int i = 0; i < 6; i++) {
            int j = lane + 32 * i;
            float4 pv = pn[j];
            float4 xv = shx[j];
            acc += xv.x * pv.x + xv.y * pv.y + xv.z * pv.z + xv.w * pv.w;
        }
#pragma unroll
        for (int off = 16; off > 0; off >>= 1)
            acc += __shfl_down_sync(0xffffffffu, acc, off);
        if (lane == 0) shsim[p] = acc;
    }
    __syncthreads();

    if (t == 0) {
        float sim[P_];
        bool used[P_];
#pragma unroll
        for (int p = 0; p < P_; p++) { sim[p] = shsim[p]; used[p] = false; }
        for (int k = 0; k < K_; k++) {
            float best = -3.4e38f;
            int bi = 0;
#pragma unroll
            for (int p = 0; p < P_; p++) {
                if (!used[p] && sim[p] > best) { best = sim[p]; bi = p; }
            }
            used[bi] = true;
            bool keep = best > 0.0f;
            int idxp = keep ? bi : -1;
            g_idx[b * K_ + k] = idxp;
            out[IDX_OFF + (size_t)b * K_ + k] = (float)idxp;
            if (keep) atomicAdd(&g_cnt[bi], 1);
        }
    }
}

// ---------------------------------------------------------------------------
// Kernel 3: grid (76, 32), block 192. PDL secondary of k2. 8 b's per block.
//  r<50        : assist row — load+stage ONCE, store 8 PE + 8 TOK rows.
//  50<=r<75    : sync on k2 once, then 8 per-b selected rows.
//  r==75, bg<16: sync on k2, reduce_sim partial, atomicAdd to SIM slot.
// ---------------------------------------------------------------------------
__global__ void k_tokens(const float4* __restrict__ prompt,
                         const float4* __restrict__ assist,
                         float* __restrict__ out) {
    __shared__ float srow[D_];
    int r = blockIdx.x;      // 0..75
    int bg = blockIdx.y;     // 0..31
    int t = threadIdx.x;     // 0..191

    if (r == ROWS_TOK) {
        if (bg >= RSB) return;
        cudaGridDependencySynchronize();
        const float4* xn = (const float4*)g_xnorm + (size_t)(bg * 16) * D4_ + t;
        float4 sx = make_float4(0.f, 0.f, 0.f, 0.f);
#pragma unroll
        for (int i = 0; i < 16; i++) {
            float4 v = xn[(size_t)i * D4_];
            sx.x += v.x; sx.y += v.y; sx.z += v.z; sx.w += v.w;
        }
        float4 kt = make_float4(0.f, 0.f, 0.f, 0.f);
#pragma unroll
        for (int p = 0; p < P_; p++) {
            float c = (float)g_cnt[p];
            float4 v = ((const float4*)g_pnorm)[(size_t)p * D4_ + t];
            kt.x += c * v.x; kt.y += c * v.y; kt.z += c * v.z; kt.w += c * v.w;
        }
        float partial = sx.x * kt.x + sx.y * kt.y + sx.z * kt.z + sx.w * kt.w;
        float tot = blk_reduce_192(partial);
        if (t == 0) atomicAdd(out + SIM_OFF, tot * (1.0f / (float)B_));
        return;
    }

    if (r < ROWS_ASSIST) {
        // b-independent row: load + stage once, fan out to 8 b's
        float4 v = assist[(size_t)r * D4_ + t];
        *(float4*)&srow[4 * t] = v;
        __syncthreads();
#pragma unroll
        for (int i = 0; i < BB; i++) {
            int b = bg * BB + i;
            __stcs((float4*)(out + PE_OFF) + (size_t)b * ROWS_PE * D4_ + (size_t)r * D4_ + t, v);
            store_row_aligned(out, TOK_OFF + (size_t)b * ROWS_TOK * D_ + (size_t)r * D_, srow, t);
        }
        return;
    }

    // selected rows: need k2's g_idx
    cudaGridDependencySynchronize();
    int rr = r - ROWS_ASSIST;
    int kk = rr / L_;
    int ll = rr % L_;
#pragma unroll
    for (int i = 0; i < BB; i++) {
        int b = bg * BB + i;
        int idx = g_idx[b * K_ + kk];
        float4 v = make_float4(0.f, 0.f, 0.f, 0.f);
        if (idx >= 0)
            v = prompt[((size_t)idx * L_ + ll) * D4_ + t];
        __stcs((float4*)(out + PE_OFF) + (size_t)b * ROWS_PE * D4_ + (size_t)r * D4_ + t, v);
        *(float4*)&srow[4 * t] = v;
        __syncthreads();
        store_row_aligned(out, TOK_OFF + (size_t)b * ROWS_TOK * D_ + (size_t)r * D_, srow, t);
        __syncthreads();
    }
}

extern "C" void kernel_launch(void* const* d_in, const int* in_sizes, int n_in,
                              void* d_out, int out_size) {
    const float4* x_embed = (const float4*)d_in[0];        // [B,S,D]
    const float4* prompt = (const float4*)d_in[1];         // [P,L,D]
    const float4* prompt_key = (const float4*)d_in[2];     // [P,D]
    const float4* assist = (const float4*)d_in[3];         // [T,L,D]
    float* out = (float*)d_out;

    k_mean_copy<<<dim3(B_, Q_ + 1), D4_>>>(x_embed, prompt_key, out);

    cudaLaunchAttribute attr[1];
    attr[0].id = cudaLaunchAttributeProgrammaticStreamSerialization;
    attr[0].val.programmaticStreamSerializationAllowed = 1;

    {
        cudaLaunchConfig_t cfg = {};
        cfg.gridDim = dim3(B_, 1, 1);
        cfg.blockDim = dim3(D4_, 1, 1);
        cfg.stream = 0;
        cfg.attrs = attr;
        cfg.numAttrs = 1;
        cudaLaunchKernelEx(&cfg, k_xnorm_topk, out);
    }
    {
        cudaLaunchConfig_t cfg = {};
        cfg.gridDim = dim3(ROWS_TOK + 1, B_ / BB, 1);
        cfg.blockDim = dim3(D4_, 1, 1);
        cfg.stream = 0;
        cfg.attrs = attr;
        cfg.numAttrs = 1;
        cudaLaunchKernelEx(&cfg, k_tokens, prompt, assist, out);
    }
}

// round 13
// speedup vs baseline: 1.0819x; 1.0215x over previous
#include <cuda_runtime.h>

#define B_ 256
#define S_ 197
#define D_ 768
#define D4_ 192
#define P_ 20
#define L_ 5
#define T_ 10
#define K_ 5
#define ROWS_TOK 75            // (T+K)*L
#define ROWS_ASSIST 50         // T*L
#define ROWS_PE 272            // ROWS_TOK + S
#define Q_ 8                   // mean/copy chunks per batch row
#define CHUNK 25               // rows per chunk (last chunk = 22)
#define RSB 16                 // reduce_sim blocks (16 b's each)

// float offsets into d_out
#define PE_OFF   0ULL
#define SIM_OFF  53477376ULL
#define TOK_OFF  53477377ULL
#define IDX_OFF  68222977ULL
#define XN_OFF   68224257ULL

// scratch (device globals; no allocations)
__device__ float g_part[Q_ * B_ * D_];
__device__ float g_xnorm[B_ * D_];
__device__ float g_pnorm[P_ * D_];
__device__ int   g_idx[B_ * K_];
__device__ int   g_cnt[P_];

// 192-thread block reduce (padded to 256 in shared)
__device__ __forceinline__ float blk_reduce_192(float v) {
    __shared__ float sh[256];
    int t = threadIdx.x;
    sh[t] = v;
    if (t < 64) sh[192 + t] = 0.f;
    __syncthreads();
    for (int s = 128; s > 0; s >>= 1) {
        if (t < s) sh[t] += sh[t + s];
        __syncthreads();
    }
    return sh[0];
}

// Write one 768-float source row (global, 16B-aligned; src==nullptr -> zeros)
// to BOTH the PE slot (float offset pe0, pe0%4==0) and the TOK slot (tok0%4==1).
// Barrier-free: TOK's shifted row is assembled in registers from two aligned
// float4 loads. All stores are aligned STG.128 (+4 edge scalars from t==191).
__device__ __forceinline__ void write_row(const float* __restrict__ src,
                                          float* __restrict__ out,
                                          size_t pe0, size_t tok0, int t) {
    float4 v, u;
    if (src) {
        v = ((const float4*)src)[t];
        u = (t < 191) ? ((const float4*)src)[t + 1] : v;
    } else {
        v = make_float4(0.f, 0.f, 0.f, 0.f);
        u = v;
    }
    __stcs((float4*)(out + pe0) + t, v);
    if (t < 191) {
        __stcs((float4*)(out + tok0 + 3) + t, make_float4(v.w, u.x, u.y, u.z));
    } else {
        float e0 = 0.f, e1 = 0.f, e2 = 0.f;
        if (src) { e0 = src[0]; e1 = src[1]; e2 = src[2]; }
        __stcs(out + tok0 + 0, e0);
        __stcs(out + tok0 + 1, e1);
        __stcs(out + tok0 + 2, e2);
        __stcs(out + tok0 + 767, v.w);   // src[767]
    }
}

// ---------------------------------------------------------------------------
// Kernel 1: grid (B, Q_+1), block 192.  (proven at BW floor — unchanged)
// ---------------------------------------------------------------------------
__global__ void k_mean_copy(const float4* __restrict__ x,
                            const float4* __restrict__ pk,
                            float* __restrict__ out) {
    int b = blockIdx.x;
    int q = blockIdx.y;
    int t = threadIdx.x;                 // 0..191

    if (q == Q_) {
        if (b == 0 && t < P_) g_cnt[t] = 0;
        if (b == 0 && t == 0) out[SIM_OFF] = 0.f;
        if (b < P_) {
            float4 v = pk[(size_t)b * D4_ + t];
            float ss = blk_reduce_192(v.x * v.x + v.y * v.y + v.z * v.z + v.w * v.w);
            float r = rsqrtf(fmaxf(ss, 1e-12f));
            float4 n = make_float4(v.x * r, v.y * r, v.z * r, v.w * r);
            ((float4*)g_pnorm)[(size_t)b * D4_ + t] = n;
        }
        cudaTriggerProgrammaticLaunchCompletion();
        return;
    }

    int s0 = q * CHUNK;
    int s1 = (q == Q_ - 1) ? S_ : s0 + CHUNK;

    const float4* xb = x + (size_t)b * S_ * D4_ + t;
    float4* ob = ((float4*)(out + PE_OFF)) + (size_t)b * ROWS_PE * D4_ + (size_t)ROWS_TOK * D4_ + t;

    float4 acc = make_float4(0.f, 0.f, 0.f, 0.f);
    int s = s0;
    for (; s + 5 <= s1; s += 5) {
        float4 v0 = __ldcs(xb + (size_t)(s + 0) * D4_);
        float4 v1 = __ldcs(xb + (size_t)(s + 1) * D4_);
        float4 v2 = __ldcs(xb + (size_t)(s + 2) * D4_);
        float4 v3 = __ldcs(xb + (size_t)(s + 3) * D4_);
        float4 v4 = __ldcs(xb + (size_t)(s + 4) * D4_);
        acc.x += v0.x + v1.x + v2.x + v3.x + v4.x;
        acc.y += v0.y + v1.y + v2.y + v3.y + v4.y;
        acc.z += v0.z + v1.z + v2.z + v3.z + v4.z;
        acc.w += v0.w + v1.w + v2.w + v3.w + v4.w;
        __stcs(ob + (size_t)(s + 0) * D4_, v0);
        __stcs(ob + (size_t)(s + 1) * D4_, v1);
        __stcs(ob + (size_t)(s + 2) * D4_, v2);
        __stcs(ob + (size_t)(s + 3) * D4_, v3);
        __stcs(ob + (size_t)(s + 4) * D4_, v4);
    }
    for (; s < s1; s++) {
        float4 v = __ldcs(xb + (size_t)s * D4_);
        acc.x += v.x; acc.y += v.y; acc.z += v.z; acc.w += v.w;
        __stcs(ob + (size_t)s * D4_, v);
    }
    ((float4*)g_part)[(size_t)q * B_ * D4_ + (size_t)b * D4_ + t] = acc;
    cudaTriggerProgrammaticLaunchCompletion();
}

// ---------------------------------------------------------------------------
// Kernel 2: grid B, block 192. PDL secondary of k1. (unchanged)
// ---------------------------------------------------------------------------
__global__ void k_xnorm_topk(float* __restrict__ out) {
    __shared__ float  sh[256];
    __shared__ float4 shx[D4_];
    __shared__ float  shsim[P_];
    int b = blockIdx.x;
    int t = threadIdx.x;

    cudaTriggerProgrammaticLaunchCompletion();
    cudaGridDependencySynchronize();

    const float4* part = (const float4*)g_part + (size_t)b * D4_ + t;
    float4 a = make_float4(0.f, 0.f, 0.f, 0.f);
#pragma unroll
    for (int q = 0; q < Q_; q++) {
        float4 c = part[(size_t)q * B_ * D4_];
        a.x += c.x; a.y += c.y; a.z += c.z; a.w += c.w;
    }
    const float inv = 1.0f / (float)S_;
    a.x *= inv; a.y *= inv; a.z *= inv; a.w *= inv;

    sh[t] = a.x * a.x + a.y * a.y + a.z * a.z + a.w * a.w;
    if (t < 64) sh[192 + t] = 0.f;
    __syncthreads();
    for (int s = 128; s > 0; s >>= 1) {
        if (t < s) sh[t] += sh[t + s];
        __syncthreads();
    }
    float r = rsqrtf(fmaxf(sh[0], 1e-12f));
    float4 n = make_float4(a.x * r, a.y * r, a.z * r, a.w * r);

    ((float4*)g_xnorm)[(size_t)b * D4_ + t] = n;

    shx[t] = n;
    __syncthreads();

    // x_norm output (row start ≡ 1 mod 4) — aligned stores from shared
    {
        const float* srow = (const float*)shx;
        size_t g0 = XN_OFF + (size_t)b * D_;
        if (t < 191) {
            float4 w = make_float4(srow[3 + 4 * t], srow[4 + 4 * t],
                                   srow[5 + 4 * t], srow[6 + 4 * t]);
            __stcs((float4*)(out + g0 + 3) + t, w);
        } else {
            __stcs(out + g0 + 0, srow[0]);
            __stcs(out + g0 + 1, srow[1]);
            __stcs(out + g0 + 2, srow[2]);
            __stcs(out + g0 + 767, srow[767]);
        }
    }

    int w = t >> 5;          // 0..5
    int lane = t & 31;
    for (int p = w; p < P_; p += 6) {
        const float4* pn = ((const float4*)g_pnorm) + (size_t)p * D4_;
        float acc = 0.f;
#pragma unroll
        for (int i = 0; i < 6; i++) {
            int j = lane + 32 * i;
            float4 pv = pn[j];
            float4 xv = shx[j];
            acc += xv.x * pv.x + xv.y * pv.y + xv.z * pv.z + xv.w * pv.w;
        }
#pragma unroll
        for (int off = 16; off > 0; off >>= 1)
            acc += __shfl_down_sync(0xffffffffu, acc, off);
        if (lane == 0) shsim[p] = acc;
    }
    __syncthreads();

    if (t == 0) {
        float sim[P_];
        bool used[P_];
#pragma unroll
        for (int p = 0; p < P_; p++) { sim[p] = shsim[p]; used[p] = false; }
        for (int k = 0; k < K_; k++) {
            float best = -3.4e38f;
            int bi = 0;
#pragma unroll
            for (int p = 0; p < P_; p++) {
                if (!used[p] && sim[p] > best) { best = sim[p]; bi = p; }
            }
            used[bi] = true;
            bool keep = best > 0.0f;
            int idxp = keep ? bi : -1;
            g_idx[b * K_ + k] = idxp;
            out[IDX_OFF + (size_t)b * K_ + k] = (float)idxp;
            if (keep) atomicAdd(&g_cnt[bi], 1);
        }
    }
}

// ---------------------------------------------------------------------------
// Kernel 3: grid (6, B), block 192. PDL secondary of k2. Barrier-free
// streaming: each block writes 15 consecutive rows -> two contiguous 45 KB
// regions (PE + TOK), k1's proven shape.
//  g<=2 : rows [15g, 15g+15) — all assist, NO dependency.
//  g==3 : rows 45-49 assist first, then grid-sync, rows 50-59 selected.
//  g==4 : grid-sync, rows 60-74 selected.
//  g==5 : b<16 -> grid-sync, reduce_sim partial, atomicAdd to SIM slot.
// ---------------------------------------------------------------------------
__global__ void k_tokens(const float* __restrict__ prompt,
                         const float* __restrict__ assist,
                         float* __restrict__ out) {
    int g = blockIdx.x;      // 0..5
    int b = blockIdx.y;
    int t = threadIdx.x;     // 0..191

    if (g == 5) {
        if (b >= RSB) return;
        cudaGridDependencySynchronize();
        const float4* xn = (const float4*)g_xnorm + (size_t)(b * 16) * D4_ + t;
        float4 sx = make_float4(0.f, 0.f, 0.f, 0.f);
#pragma unroll
        for (int i = 0; i < 16; i++) {
            float4 v = xn[(size_t)i * D4_];
            sx.x += v.x; sx.y += v.y; sx.z += v.z; sx.w += v.w;
        }
        float4 kt = make_float4(0.f, 0.f, 0.f, 0.f);
#pragma unroll
        for (int p = 0; p < P_; p++) {
            float c = (float)g_cnt[p];
            float4 v = ((const float4*)g_pnorm)[(size_t)p * D4_ + t];
            kt.x += c * v.x; kt.y += c * v.y; kt.z += c * v.z; kt.w += c * v.w;
        }
        float partial = sx.x * kt.x + sx.y * kt.y + sx.z * kt.z + sx.w * kt.w;
        float tot = blk_reduce_192(partial);
        if (t == 0) atomicAdd(out + SIM_OFF, tot * (1.0f / (float)B_));
        return;
    }

    size_t pe0  = PE_OFF  + (size_t)b * ROWS_PE  * D_;
    size_t tok0 = TOK_OFF + (size_t)b * ROWS_TOK * D_;

    if (g <= 2) {
        int r0 = g * 15;
#pragma unroll 3
        for (int i = 0; i < 15; i++) {
            int r = r0 + i;
            write_row(assist + (size_t)r * D_, out,
                      pe0 + (size_t)r * D_, tok0 + (size_t)r * D_, t);
        }
        return;
    }

    if (g == 3) {
#pragma unroll
        for (int i = 0; i < 5; i++) {
            int r = 45 + i;
            write_row(assist + (size_t)r * D_, out,
                      pe0 + (size_t)r * D_, tok0 + (size_t)r * D_, t);
        }
    }

    cudaGridDependencySynchronize();   // need k2's g_idx

    int rs = (g == 3) ? 50 : 60;
    int re = (g == 3) ? 60 : 75;
#pragma unroll 5
    for (int r = rs; r < re; r++) {
        int rr = r - ROWS_ASSIST;
        int idx = g_idx[b * K_ + rr / L_];
        const float* src = (idx >= 0)
            ? (prompt + ((size_t)idx * L_ + (rr % L_)) * D_) : (const float*)0;
        write_row(src, out, pe0 + (size_t)r * D_, tok0 + (size_t)r * D_, t);
    }
}

extern "C" void kernel_launch(void* const* d_in, const int* in_sizes, int n_in,
                              void* d_out, int out_size) {
    const float4* x_embed = (const float4*)d_in[0];        // [B,S,D]
    const float* prompt = (const float*)d_in[1];           // [P,L,D]
    const float4* prompt_key = (const float4*)d_in[2];     // [P,D]
    const float* assist = (const float*)d_in[3];           // [T,L,D]
    float* out = (float*)d_out;

    k_mean_copy<<<dim3(B_, Q_ + 1), D4_>>>(x_embed, prompt_key, out);

    cudaLaunchAttribute attr[1];
    attr[0].id = cudaLaunchAttributeProgrammaticStreamSerialization;
    attr[0].val.programmaticStreamSerializationAllowed = 1;

    {
        cudaLaunchConfig_t cfg = {};
        cfg.gridDim = dim3(B_, 1, 1);
        cfg.blockDim = dim3(D4_, 1, 1);
        cfg.stream = 0;
        cfg.attrs = attr;
        cfg.numAttrs = 1;
        cudaLaunchKernelEx(&cfg, k_xnorm_topk, out);
    }
    {
        cudaLaunchConfig_t cfg = {};
        cfg.gridDim = dim3(6, B_, 1);
        cfg.blockDim = dim3(D4_, 1, 1);
        cfg.stream = 0;
        cfg.attrs = attr;
        cfg.numAttrs = 1;
        cudaLaunchKernelEx(&cfg, k_tokens, prompt, assist, out);
    }
}